// round 5
// baseline (speedup 1.0000x reference)
#include <cuda_runtime.h>
#include <cuda_bf16.h>

// Problem constants
#define T_DIM 32768
#define D_DIM 1024
#define L_CHUNK 32
#define C_CHUNKS (T_DIM / L_CHUNK)   // 1024

#define ETA_MU_F 0.01f
#define A_MU_F   0.99f
#define ETA_V_F  0.02f
#define CV_F     0.98f

// Per-(chunk, column) aggregates. Static device scratch (no allocation allowed).
__device__ float g_cmu[C_CHUNKS * D_DIM];    // chunk-local zero-state EWMA end value
__device__ float g_P[C_CHUNKS * D_DIM];      // var quadratic: constant term
__device__ float g_Q[C_CHUNKS * D_DIM];      // var quadratic: linear coefficient
__device__ float g_sum[C_CHUNKS * D_DIM];    // chunk sum of x
__device__ float g_ss[C_CHUNKS * D_DIM];     // chunk sum of x^2
__device__ float g_mus[C_CHUNKS * D_DIM];    // composed mu at chunk entry
__device__ float g_vas[C_CHUNKS * D_DIM];    // composed var at chunk entry

// ---------------------------------------------------------------------------
// Pass 1: one vectorized read of x. Per (chunk c, column d):
//   sum, sumsq                       -> for mu0 / std0
//   m   (zero-state chunk EWMA)      -> c_mu aggregate
//   Pa = sum cv^{L-1-i} u_i^2,  Qa = sum cv^{L-1-i} u_i a^{i+1},  u_i = x_i - m_i
// Each thread owns 4 adjacent columns (float4). L=32 -> grid of 2048 blocks.
// ---------------------------------------------------------------------------
__global__ __launch_bounds__(128) void p1_kernel(const float4* __restrict__ x4) {
    const int d4 = blockIdx.x * blockDim.x + threadIdx.x;   // 0..255 (column group)
    const int c  = blockIdx.y;
    const float4* xp = x4 + (size_t)c * L_CHUNK * (D_DIM / 4) + d4;

    float m[4]   = {0.f, 0.f, 0.f, 0.f};
    float sum[4] = {0.f, 0.f, 0.f, 0.f};
    float ss[4]  = {0.f, 0.f, 0.f, 0.f};
    float Pa[4]  = {0.f, 0.f, 0.f, 0.f};
    float Qa[4]  = {0.f, 0.f, 0.f, 0.f};
    float g = A_MU_F;  // a^{i+1}

    #pragma unroll 8
    for (int i = 0; i < L_CHUNK; i++) {
        float4 xv4 = xp[(size_t)i * (D_DIM / 4)];
        float xv[4] = {xv4.x, xv4.y, xv4.z, xv4.w};
        #pragma unroll
        for (int k = 0; k < 4; k++) {
            float v = xv[k];
            sum[k] += v;
            ss[k] = fmaf(v, v, ss[k]);
            m[k] = fmaf(ETA_MU_F, v - m[k], m[k]);   // reference rounding form
            float u = v - m[k];
            Pa[k] = fmaf(CV_F, Pa[k], u * u);
            Qa[k] = fmaf(CV_F, Qa[k], u * g);
        }
        g *= A_MU_F;
    }
    #pragma unroll
    for (int k = 0; k < 4; k++) {
        const int idx = c * D_DIM + d4 * 4 + k;
        g_cmu[idx] = m[k];
        g_P[idx]   = ETA_V_F * Pa[k];
        g_Q[idx]   = ETA_V_F * Qa[k];
        g_sum[idx] = sum[k];
        g_ss[idx]  = ss[k];
    }
}

// ---------------------------------------------------------------------------
// Pass 2: one thread per column. L2-hot (~20MB of aggregates).
//   mu0 = mean, var0 = unbiased std (stored into the 'var' slot, as reference).
//   Sequentially compose 1024 chunk-entry states:
//     mu_next  = a^L  * mu  + c_mu[c]
//     var_next = cv^L * var + (P[c] - 2 Q[c] mu + R mu^2)
// ---------------------------------------------------------------------------
__global__ __launch_bounds__(256) void p2_kernel() {
    const int d = blockIdx.x * blockDim.x + threadIdx.x;
    if (d >= D_DIM) return;

    double tsum = 0.0, tss = 0.0;
    #pragma unroll 8
    for (int c = 0; c < C_CHUNKS; c++) {
        tsum += (double)g_sum[c * D_DIM + d];
        tss  += (double)g_ss[c * D_DIM + d];
    }
    const double Td = (double)T_DIM;
    float mu0  = (float)(tsum / Td);
    float var0 = (float)sqrt((tss - tsum * tsum / Td) / (Td - 1.0));

    // Constants in double: a^L, cv^L, R = sum_i ev * cv^{L-1-i} * a^{2(i+1)}
    double Am = 1.0, Av = 1.0, R = 0.0, g2 = 0.9801;  // a^2
    for (int i = 0; i < L_CHUNK; i++) {
        Am *= 0.99;
        Av *= 0.98;
        R = R * 0.98 + 0.02 * g2;
        g2 *= 0.9801;
    }
    const float AmL = (float)Am;
    const float AvL = (float)Av;
    const float Rc  = (float)R;

    float s = mu0, v = var0;
    #pragma unroll 8
    for (int c = 0; c < C_CHUNKS; c++) {
        const int idx = c * D_DIM + d;
        g_mus[idx] = s;
        g_vas[idx] = v;
        float cmu = g_cmu[idx];
        float Pv  = g_P[idx];
        float Qv  = g_Q[idx];
        float cvar = fmaf(s, fmaf(s, Rc, -2.0f * Qv), Pv);  // P - 2Qs + Rs^2
        v = fmaf(AvL, v, cvar);
        s = fmaf(AmL, s, cmu);
    }
}

// ---------------------------------------------------------------------------
// Pass 5: second vectorized read of x. Replay each chunk serially with the
// exact fp32 arithmetic of the reference; write norm, mu, var as float4.
// ---------------------------------------------------------------------------
__global__ __launch_bounds__(128) void p5_kernel(const float4* __restrict__ x4,
                                                 float4* __restrict__ out4) {
    float4* __restrict__ norm = out4;                                  // [T, D/4]
    float4* __restrict__ info = out4 + (size_t)T_DIM * (D_DIM / 4);    // [T, 2D/4]

    const int d4 = blockIdx.x * blockDim.x + threadIdx.x;  // 0..255
    const int c  = blockIdx.y;
    const int d0 = d4 * 4;

    float mu[4], var[4];
    #pragma unroll
    for (int k = 0; k < 4; k++) {
        mu[k]  = g_mus[c * D_DIM + d0 + k];
        var[k] = g_vas[c * D_DIM + d0 + k];
    }

    const size_t tbase = (size_t)c * L_CHUNK;
    #pragma unroll 4
    for (int i = 0; i < L_CHUNK; i++) {
        const size_t t = tbase + i;
        float4 xv4 = x4[t * (D_DIM / 4) + d4];
        float xv[4] = {xv4.x, xv4.y, xv4.z, xv4.w};
        float nv[4];
        #pragma unroll
        for (int k = 0; k < 4; k++) {
            mu[k] = fmaf(ETA_MU_F, xv[k] - mu[k], mu[k]);          // mu += eta*(x-mu)
            float dd = xv[k] - mu[k];
            var[k] = fmaf(ETA_V_F, dd * dd, CV_F * var[k]);         // 0.98*var + 0.02*dd^2
            nv[k] = dd * rsqrtf(var[k]);                            // (x-mu)/sqrt(var)
        }
        norm[t * (D_DIM / 4) + d4]                    = make_float4(nv[0], nv[1], nv[2], nv[3]);
        info[t * (2 * D_DIM / 4) + d4]                = make_float4(mu[0], mu[1], mu[2], mu[3]);
        info[t * (2 * D_DIM / 4) + (D_DIM / 4) + d4]  = make_float4(var[0], var[1], var[2], var[3]);
    }
}

extern "C" void kernel_launch(void* const* d_in, const int* in_sizes, int n_in,
                              void* d_out, int out_size) {
    const float4* x4 = (const float4*)d_in[0];
    float4* out4 = (float4*)d_out;

    dim3 b(128);
    dim3 g1((D_DIM / 4) / 128, C_CHUNKS);   // (2, 1024)
    p1_kernel<<<g1, b>>>(x4);
    p2_kernel<<<D_DIM / 256, dim3(256)>>>();
    p5_kernel<<<g1, b>>>(x4, out4);
}

// round 7
// speedup vs baseline: 4.2889x; 4.2889x over previous
#include <cuda_runtime.h>
#include <cuda_bf16.h>

// Problem constants
#define T_DIM 32768
#define D_DIM 1024
#define L_CHUNK 32
#define C_CHUNKS (T_DIM / L_CHUNK)      // 1024
#define SUPER 32                        // chunks per super-chunk
#define NSUP (C_CHUNKS / SUPER)         // 32 super-chunks

#define ETA_MU_F 0.01f
#define A_MU_F   0.99f
#define ETA_V_F  0.02f
#define CV_F     0.98f

// Static device scratch (no allocation allowed).
// Per-chunk aggregates (from P1):
__device__ float g_cmu[C_CHUNKS * D_DIM];
__device__ float g_P[C_CHUNKS * D_DIM];
__device__ float g_Q[C_CHUNKS * D_DIM];
__device__ float g_sum[C_CHUNKS * D_DIM];
__device__ float g_ss[C_CHUNKS * D_DIM];
// Per-chunk entry states (consumed by P5):
__device__ float g_mus[C_CHUNKS * D_DIM];
__device__ float g_vas[C_CHUNKS * D_DIM];
// Per-super-chunk aggregates / entry states:
__device__ float s_c[NSUP * D_DIM];
__device__ float s_P[NSUP * D_DIM];
__device__ float s_Q[NSUP * D_DIM];
__device__ float s_sum[NSUP * D_DIM];
__device__ float s_ss[NSUP * D_DIM];
__device__ float s_mus[NSUP * D_DIM];
__device__ float s_vas[NSUP * D_DIM];

// Per-chunk constants over literals: fully unrolled so ptxas constant-folds
// the double-precision preamble instead of emitting a DFMA chain at runtime.
__device__ __forceinline__ void chunk_consts(float& Amc, float& Avc, float& Rc) {
    double Am = 1.0, Av = 1.0, R = 0.0, g2 = 0.9801;  // a^2
    #pragma unroll
    for (int i = 0; i < L_CHUNK; i++) {
        Am *= 0.99; Av *= 0.98;
        R = R * 0.98 + 0.02 * g2;
        g2 *= 0.9801;
    }
    Amc = (float)Am; Avc = (float)Av; Rc = (float)R;
}

// ---------------------------------------------------------------------------
// Pass 1: one vectorized read of x -> per-chunk aggregates.
//   u_i = x_i - m_i (m = zero-state chunk EWMA)
//   Pa = sum cv^{L-1-i} u_i^2, Qa = sum cv^{L-1-i} u_i a^{i+1}
// Each thread owns 4 adjacent columns (float4). Grid (2, 1024).
// ---------------------------------------------------------------------------
__global__ __launch_bounds__(128) void p1_kernel(const float4* __restrict__ x4) {
    const int d4 = blockIdx.x * blockDim.x + threadIdx.x;   // column group 0..255
    const int c  = blockIdx.y;
    const float4* xp = x4 + (size_t)c * L_CHUNK * (D_DIM / 4) + d4;

    float m[4]   = {0.f,0.f,0.f,0.f};
    float sum[4] = {0.f,0.f,0.f,0.f};
    float ss[4]  = {0.f,0.f,0.f,0.f};
    float Pa[4]  = {0.f,0.f,0.f,0.f};
    float Qa[4]  = {0.f,0.f,0.f,0.f};
    float g = A_MU_F;  // a^{i+1}

    #pragma unroll 8
    for (int i = 0; i < L_CHUNK; i++) {
        float4 xv4 = xp[(size_t)i * (D_DIM / 4)];
        float xv[4] = {xv4.x, xv4.y, xv4.z, xv4.w};
        #pragma unroll
        for (int k = 0; k < 4; k++) {
            float v = xv[k];
            sum[k] += v;
            ss[k] = fmaf(v, v, ss[k]);
            m[k] = fmaf(ETA_MU_F, v - m[k], m[k]);   // reference rounding form
            float u = v - m[k];
            Pa[k] = fmaf(CV_F, Pa[k], u * u);
            Qa[k] = fmaf(CV_F, Qa[k], u * g);
        }
        g *= A_MU_F;
    }
    #pragma unroll
    for (int k = 0; k < 4; k++) {
        const int idx = c * D_DIM + d4 * 4 + k;
        g_cmu[idx] = m[k];
        g_P[idx]   = ETA_V_F * Pa[k];
        g_Q[idx]   = ETA_V_F * Qa[k];
        g_sum[idx] = sum[k];
        g_ss[idx]  = ss[k];
    }
}

// ---------------------------------------------------------------------------
// Pass 2a: compose 32 chunk aggregates -> one super-chunk aggregate.
// One thread per (super-chunk, column): 32768 threads, coalesced over d.
// Composition (acc A, then chunk B with constants Amc/Avc/Rc):
//   P' = Avc*P + (Pb - 2 Qb c + Rc c^2)
//   Q' = Avc*Q + Am*(Qb - Rc*c)
//   c' = Amc*c + cb ;  Am' = Amc*Am
// ---------------------------------------------------------------------------
__global__ __launch_bounds__(256) void p2a_kernel() {
    const int tid = blockIdx.x * blockDim.x + threadIdx.x;
    const int d = tid % D_DIM;
    const int gsup = tid / D_DIM;
    if (gsup >= NSUP) return;

    float Amc, Avc, Rc;
    chunk_consts(Amc, Avc, Rc);

    float c = 0.f, P = 0.f, Q = 0.f, Am = 1.f;
    float psum = 0.f, pss = 0.f;

    int idx = gsup * SUPER * D_DIM + d;
    #pragma unroll 4
    for (int j = 0; j < SUPER; j++, idx += D_DIM) {
        float cb = g_cmu[idx];
        float Pb = g_P[idx];
        float Qb = g_Q[idx];
        psum += g_sum[idx];
        pss  += g_ss[idx];
        P = fmaf(Avc, P, fmaf(c, fmaf(Rc, c, -2.f * Qb), Pb));   // Avc*P + Pb - 2Qb c + Rc c^2
        Q = fmaf(Avc, Q, Am * fmaf(-Rc, c, Qb));                  // Avc*Q + Am*(Qb - Rc c)
        c = fmaf(Amc, c, cb);
        Am *= Amc;
    }
    const int sidx = gsup * D_DIM + d;
    s_c[sidx] = c;
    s_P[sidx] = P;
    s_Q[sidx] = Q;
    s_sum[sidx] = psum;
    s_ss[sidx]  = pss;
}

// ---------------------------------------------------------------------------
// Pass 2b: per column. Reduce 32 partial sums -> mu0/var0 (double), then fold
// only 32 super aggregates serially -> per-super entry states.
// ---------------------------------------------------------------------------
__global__ __launch_bounds__(256) void p2b_kernel() {
    const int d = blockIdx.x * blockDim.x + threadIdx.x;
    if (d >= D_DIM) return;

    double tsum = 0.0, tss = 0.0;
    #pragma unroll
    for (int g = 0; g < NSUP; g++) {
        tsum += (double)s_sum[g * D_DIM + d];
        tss  += (double)s_ss[g * D_DIM + d];
    }
    const double Td = (double)T_DIM;
    float mu0  = (float)(tsum / Td);
    float var0 = (float)sqrt((tss - tsum * tsum / Td) / (Td - 1.0));

    // chunk constants, then super-level Am_s, Av_s, R_s by folding 32 chunks
    float Amc, Avc, Rc;
    chunk_consts(Amc, Avc, Rc);
    double Rs = 0.0, Amd = 1.0, Avs = 1.0, Ams = 1.0;
    #pragma unroll
    for (int j = 0; j < SUPER; j++) {
        Rs = (double)Avc * Rs + (double)Rc * Amd * Amd;
        Amd *= (double)Amc;
        Avs *= (double)Avc;
        Ams *= (double)Amc;
    }
    const float Am_s = (float)Ams, Av_s = (float)Avs, R_s = (float)Rs;

    float s = mu0, v = var0;
    #pragma unroll
    for (int g = 0; g < NSUP; g++) {
        const int sidx = g * D_DIM + d;
        s_mus[sidx] = s;
        s_vas[sidx] = v;
        float cg = s_c[sidx];
        float Pg = s_P[sidx];
        float Qg = s_Q[sidx];
        v = fmaf(Av_s, v, fmaf(s, fmaf(s, R_s, -2.f * Qg), Pg));
        s = fmaf(Am_s, s, cg);
    }
}

// ---------------------------------------------------------------------------
// Pass 2c: expand within each super-chunk -> per-chunk entry states.
// One thread per (super-chunk, column): 32768 threads, 32 steps each.
// ---------------------------------------------------------------------------
__global__ __launch_bounds__(256) void p2c_kernel() {
    const int tid = blockIdx.x * blockDim.x + threadIdx.x;
    const int d = tid % D_DIM;
    const int gsup = tid / D_DIM;
    if (gsup >= NSUP) return;

    float Amc, Avc, Rc;
    chunk_consts(Amc, Avc, Rc);

    const int sidx = gsup * D_DIM + d;
    float s = s_mus[sidx];
    float v = s_vas[sidx];

    int idx = gsup * SUPER * D_DIM + d;
    #pragma unroll 4
    for (int j = 0; j < SUPER; j++, idx += D_DIM) {
        g_mus[idx] = s;
        g_vas[idx] = v;
        float cb = g_cmu[idx];
        float Pb = g_P[idx];
        float Qb = g_Q[idx];
        v = fmaf(Avc, v, fmaf(s, fmaf(s, Rc, -2.f * Qb), Pb));
        s = fmaf(Amc, s, cb);
    }
}

// ---------------------------------------------------------------------------
// Pass 5: second vectorized read of x. Replay each chunk serially with the
// exact fp32 arithmetic of the reference; write norm, mu, var as float4.
// ---------------------------------------------------------------------------
__global__ __launch_bounds__(128) void p5_kernel(const float4* __restrict__ x4,
                                                 float4* __restrict__ out4) {
    float4* __restrict__ norm = out4;                                  // [T, D/4]
    float4* __restrict__ info = out4 + (size_t)T_DIM * (D_DIM / 4);    // [T, 2D/4]

    const int d4 = blockIdx.x * blockDim.x + threadIdx.x;  // 0..255
    const int c  = blockIdx.y;
    const int d0 = d4 * 4;

    float mu[4], var[4];
    #pragma unroll
    for (int k = 0; k < 4; k++) {
        mu[k]  = g_mus[c * D_DIM + d0 + k];
        var[k] = g_vas[c * D_DIM + d0 + k];
    }

    const size_t tbase = (size_t)c * L_CHUNK;
    #pragma unroll 4
    for (int i = 0; i < L_CHUNK; i++) {
        const size_t t = tbase + i;
        float4 xv4 = x4[t * (D_DIM / 4) + d4];
        float xv[4] = {xv4.x, xv4.y, xv4.z, xv4.w};
        float nv[4];
        #pragma unroll
        for (int k = 0; k < 4; k++) {
            mu[k] = fmaf(ETA_MU_F, xv[k] - mu[k], mu[k]);          // mu += eta*(x-mu)
            float dd = xv[k] - mu[k];
            var[k] = fmaf(ETA_V_F, dd * dd, CV_F * var[k]);         // 0.98*var + 0.02*dd^2
            nv[k] = dd * rsqrtf(var[k]);                            // (x-mu)/sqrt(var)
        }
        norm[t * (D_DIM / 4) + d4]                    = make_float4(nv[0], nv[1], nv[2], nv[3]);
        info[t * (2 * D_DIM / 4) + d4]                = make_float4(mu[0], mu[1], mu[2], mu[3]);
        info[t * (2 * D_DIM / 4) + (D_DIM / 4) + d4]  = make_float4(var[0], var[1], var[2], var[3]);
    }
}

extern "C" void kernel_launch(void* const* d_in, const int* in_sizes, int n_in,
                              void* d_out, int out_size) {
    const float4* x4 = (const float4*)d_in[0];
    float4* out4 = (float4*)d_out;

    dim3 b(128);
    dim3 g1((D_DIM / 4) / 128, C_CHUNKS);   // (2, 1024)
    p1_kernel<<<g1, b>>>(x4);
    p2a_kernel<<<(NSUP * D_DIM) / 256, 256>>>();
    p2b_kernel<<<D_DIM / 256, 256>>>();
    p2c_kernel<<<(NSUP * D_DIM) / 256, 256>>>();
    p5_kernel<<<g1, b>>>(x4, out4);
}